// round 5
// baseline (speedup 1.0000x reference)
#include <cuda_runtime.h>
#include <cuda_bf16.h>
#include <cstdint>
#include <math.h>

// Problem constants
#define Hq    12
#define HKV   2
#define NG    6          // Hq / HKV
#define Dh    128
#define HID   1536
#define Bc    4
#define Sc    2048
#define Tn    (Bc*Sc)    // 8192 tokens
#define NQKV  2048       // Hq*Dh + 2*HKV*Dh
#define NSLOTS 16384
#define OUT_ELEMS   ((size_t)Tn*HID)          // 12582912
#define CACHE_ELEMS ((size_t)NSLOTS*HKV*Dh)   // 4194304

// Scratch (device globals; no runtime allocation allowed)
__device__ float g_qkv[(size_t)Tn * NQKV];    // 67 MB
__device__ float g_attn[(size_t)Tn * HID];    // 50 MB

// Pair-interleave permutation within each 8-column group:
// true col c -> position (c&~7) | ((c&3)<<1) | ((c>>2)&1)
// => (k, k+4) land at adjacent positions (2k', 2k'+1), enabling LDS.64 frags.
#define KPERM(c) (((c) & ~7) | ((((c) & 3) << 1) | (((c) >> 2) & 1)))

// ===========================================================================
// TF32 helpers (portable to plain sm_103 target: no 'a'-gated instructions)
// ===========================================================================
__device__ __forceinline__ float to_tf32(float x) {
    float y;
    asm("cvt.rna.tf32.f32 %0, %1;" : "=f"(y) : "f"(x));
    return y;
}

__device__ __forceinline__ void mma_tf32_16x8x8(
    float& d0, float& d1, float& d2, float& d3,
    float a0, float a1, float a2, float a3,
    float b0, float b1)
{
    uint32_t A0 = __float_as_uint(a0), A1 = __float_as_uint(a1);
    uint32_t A2 = __float_as_uint(a2), A3 = __float_as_uint(a3);
    uint32_t B0 = __float_as_uint(b0), B1 = __float_as_uint(b1);
    asm volatile(
        "mma.sync.aligned.m16n8k8.row.col.f32.tf32.tf32.f32 "
        "{%0,%1,%2,%3}, {%4,%5,%6,%7}, {%8,%9}, {%0,%1,%2,%3};"
        : "+f"(d0), "+f"(d1), "+f"(d2), "+f"(d3)
        : "r"(A0), "r"(A1), "r"(A2), "r"(A3), "r"(B0), "r"(B1));
}

// ===========================================================================
// TF32 tensor-core GEMM: C[M,N] = A[M,K] @ B[N,K]^T (+ bias[N])
// 128x128 tile, BK=32, 8 warps (2x4), double-buffered smem,
// pair-interleaved k layout -> LDS.64 fragment loads, stride 40 (8 mod 32).
// ===========================================================================
#define GSTR 40
#define GBUF (128 * GSTR)
#define G_SMEM_FLOATS (4 * GBUF)

__global__ __launch_bounds__(256, 2) void gemm_mma_kernel(
    const float* __restrict__ A, const float* __restrict__ Bw,
    const float* __restrict__ bias, float* __restrict__ C,
    int M, int N, int K)
{
    extern __shared__ float smem[];
    float* As = smem;
    float* Bs = smem + 2 * GBUF;

    const int tid  = threadIdx.x;
    const int wid  = tid >> 5;
    const int lane = tid & 31;
    const int gid  = lane >> 2;
    const int tig  = lane & 3;

    const int m0 = blockIdx.y * 128;
    const int n0 = blockIdx.x * 128;
    const int wm0 = (wid >> 2) * 64;
    const int wn0 = (wid & 3) * 32;

    float4 ar[4], br[4];

    float acc[4][4][4];
#pragma unroll
    for (int mi = 0; mi < 4; mi++)
#pragma unroll
        for (int ni = 0; ni < 4; ni++)
#pragma unroll
            for (int r = 0; r < 4; r++) acc[mi][ni][r] = 0.f;

    const int nchunks = K >> 5;

#pragma unroll
    for (int i = 0; i < 4; i++) {
        const int idx = tid + i * 256;
        const int r  = idx >> 3;
        const int cg = (idx & 7) << 2;
        ar[i] = *(const float4*)(A  + (size_t)(m0 + r) * K + cg);
        br[i] = *(const float4*)(Bw + (size_t)(n0 + r) * K + cg);
    }
#pragma unroll
    for (int i = 0; i < 4; i++) {
        const int idx = tid + i * 256;
        const int r  = idx >> 3;
        const int cg = (idx & 7) << 2;
        const int pb = (cg & ~7) | ((cg >> 2) & 1);   // perm base, stride 2
        float* pa = As + r * GSTR + pb;
        pa[0] = to_tf32(ar[i].x); pa[2] = to_tf32(ar[i].y);
        pa[4] = to_tf32(ar[i].z); pa[6] = to_tf32(ar[i].w);
        float* pbv = Bs + r * GSTR + pb;
        pbv[0] = to_tf32(br[i].x); pbv[2] = to_tf32(br[i].y);
        pbv[4] = to_tf32(br[i].z); pbv[6] = to_tf32(br[i].w);
    }
    __syncthreads();

    int p = 0;
    for (int c = 0; c < nchunks; c++) {
        const bool more = (c + 1) < nchunks;
        if (more) {
            const int kc = (c + 1) << 5;
#pragma unroll
            for (int i = 0; i < 4; i++) {
                const int idx = tid + i * 256;
                const int r  = idx >> 3;
                const int cg = (idx & 7) << 2;
                ar[i] = *(const float4*)(A  + (size_t)(m0 + r) * K + kc + cg);
                br[i] = *(const float4*)(Bw + (size_t)(n0 + r) * K + kc + cg);
            }
        }

        const float* Ab = As + p * GBUF;
        const float* Bb = Bs + p * GBUF;
#pragma unroll
        for (int ks = 0; ks < 4; ks++) {
            const int kcb = ks * 8;
            float2 bfr[4];
#pragma unroll
            for (int ni = 0; ni < 4; ni++) {
                const int rB = wn0 + ni * 8 + gid;
                bfr[ni] = *(const float2*)(Bb + rB * GSTR + kcb + 2 * tig);
            }
#pragma unroll
            for (int mi = 0; mi < 4; mi++) {
                const int r = wm0 + mi * 16 + gid;
                const float2 fa0 = *(const float2*)(Ab + r * GSTR + kcb + 2 * tig);
                const float2 fa1 = *(const float2*)(Ab + (r + 8) * GSTR + kcb + 2 * tig);
#pragma unroll
                for (int ni = 0; ni < 4; ni++) {
                    mma_tf32_16x8x8(acc[mi][ni][0], acc[mi][ni][1],
                                    acc[mi][ni][2], acc[mi][ni][3],
                                    fa0.x, fa1.x, fa0.y, fa1.y,
                                    bfr[ni].x, bfr[ni].y);
                }
            }
        }

        if (more) {
            float* Aw = As + (p ^ 1) * GBUF;
            float* Bww = Bs + (p ^ 1) * GBUF;
#pragma unroll
            for (int i = 0; i < 4; i++) {
                const int idx = tid + i * 256;
                const int r  = idx >> 3;
                const int cg = (idx & 7) << 2;
                const int pb = (cg & ~7) | ((cg >> 2) & 1);
                float* pa = Aw + r * GSTR + pb;
                pa[0] = to_tf32(ar[i].x); pa[2] = to_tf32(ar[i].y);
                pa[4] = to_tf32(ar[i].z); pa[6] = to_tf32(ar[i].w);
                float* pbv = Bww + r * GSTR + pb;
                pbv[0] = to_tf32(br[i].x); pbv[2] = to_tf32(br[i].y);
                pbv[4] = to_tf32(br[i].z); pbv[6] = to_tf32(br[i].w);
            }
        }
        __syncthreads();
        p ^= 1;
    }

#pragma unroll
    for (int mi = 0; mi < 4; mi++) {
        const int row = m0 + wm0 + mi * 16 + gid;
#pragma unroll
        for (int ni = 0; ni < 4; ni++) {
            const int col = n0 + wn0 + ni * 8 + 2 * tig;
            float b0 = 0.f, b1 = 0.f;
            if (bias) { b0 = bias[col]; b1 = bias[col + 1]; }
            float2 v0 = make_float2(acc[mi][ni][0] + b0, acc[mi][ni][1] + b1);
            float2 v1 = make_float2(acc[mi][ni][2] + b0, acc[mi][ni][3] + b1);
            *(float2*)(C + (size_t)row * N + col)       = v0;
            *(float2*)(C + (size_t)(row + 8) * N + col) = v1;
        }
    }
}

// ---------------------------------------------------------------------------
// RoPE (in place on g_qkv q,k heads) + scatter rotated k and raw v to caches.
// ---------------------------------------------------------------------------
__global__ void rope_scatter_kernel(float* __restrict__ qkv,
                                    const float* __restrict__ cosb,
                                    const float* __restrict__ sinb,
                                    const int* __restrict__ slot,
                                    float* __restrict__ kc,
                                    float* __restrict__ vc) {
    const int r = blockIdx.x;
    float* row = qkv + (size_t)r * NQKV;
    const float* cr = cosb + (size_t)r * Dh;
    const float* sr = sinb + (size_t)r * Dh;
    const int s = slot[r];

    for (int idx = threadIdx.x; idx < 14 * 64; idx += blockDim.x) {
        const int head = idx >> 6;
        const int d = idx & 63;
        float* hp = row + head * Dh;
        const float x1 = hp[d], x2 = hp[d + 64];
        const float c1 = cr[d], s1 = sr[d];
        const float c2 = cr[d + 64], s2 = sr[d + 64];
        const float o1 = x1 * c1 - x2 * s1;
        const float o2 = x2 * c2 + x1 * s2;
        hp[d] = o1;
        hp[d + 64] = o2;
        if (head >= Hq) {
            const int kh = head - Hq;
            float* kdst = kc + ((size_t)s * HKV + kh) * Dh;
            kdst[d] = o1;
            kdst[d + 64] = o2;
        }
    }
    for (int idx = threadIdx.x; idx < HKV * Dh; idx += blockDim.x) {
        vc[(size_t)s * (HKV * Dh) + idx] = row[Hq * Dh + HKV * Dh + idx];
    }
}

// ===========================================================================
// Tensor-core causal GQA flash attention (tf32 mma.sync), pair-interleaved.
// CTA: 128-query tile per (head, batch). 512 threads = 16 warps (8M x 2N).
//   QK: warp m16 x n32, k=128.   PV: warp m16 x n64, k=64 (V transposed).
// ===========================================================================
#define AQSTR 136       // Q/K stride: 136 mod 32 == 8 -> conflict-free LDS.64
#define ASSTR 72        // scores stride (72 mod 32 == 8)
#define VTSTR 72        // transposed-V stride
#define ATT_Q_FL   (128 * AQSTR)
#define ATT_K_FL   (64 * AQSTR)
#define ATT_V_FL   (128 * VTSTR)
#define ATT_S_FL   (128 * ASSTR)
#define ATT2_SMEM_FLOATS (ATT_Q_FL + ATT_K_FL + ATT_V_FL + ATT_S_FL + 3 * 128)

__global__ __launch_bounds__(512) void attn_mma_kernel(
    const float* __restrict__ qkv, float* __restrict__ out)
{
    extern __shared__ float sm[];
    float* Qs = sm;
    float* Ks = Qs + ATT_Q_FL;
    float* Vt = Ks + ATT_K_FL;          // [128 dh][64 keys perm]
    float* Ss = Vt + ATT_V_FL;
    float* mrow = Ss + ATT_S_FL;
    float* lrow = mrow + 128;
    float* arow = lrow + 128;

    const int qt = (gridDim.x - 1) - blockIdx.x;   // heavy tiles first
    const int h = blockIdx.y, b = blockIdx.z;
    const int kh = h / NG;
    const int tid = threadIdx.x;
    const int wid = tid >> 5;
    const int lane = tid & 31;
    const int gid = lane >> 2;
    const int tig = lane & 3;
    const int wm = wid >> 1;          // 0..7 -> 16-row strip
    const int wn = wid & 1;           // 0..1
    const int q0 = qt * 128;
    const int rowbase = b * Sc;
    const float scale = 0.08838834764831845f;   // 1/sqrt(128)

    // --- load Q tile (tf32, pair-interleaved cols) ---
    for (int i = tid; i < 128 * 32; i += 512) {
        const int r = i >> 5;
        const int col = (i & 31) << 2;
        float4 v = *(const float4*)(qkv + (size_t)(rowbase + q0 + r) * NQKV + h * Dh + col);
        const int pb = (col & ~7) | ((col >> 2) & 1);
        float* p = Qs + r * AQSTR + pb;
        p[0] = to_tf32(v.x); p[2] = to_tf32(v.y);
        p[4] = to_tf32(v.z); p[6] = to_tf32(v.w);
    }
    if (tid < 128) { mrow[tid] = -1e30f; lrow[tid] = 0.f; }

    float oacc[8][4];
#pragma unroll
    for (int nt = 0; nt < 8; nt++)
#pragma unroll
        for (int r = 0; r < 4; r++) oacc[nt][r] = 0.f;

    __syncthreads();

    const int nkt = 2 * qt + 2;
    for (int kt = 0; kt < nkt; kt++) {
        const int k0 = kt * 64;

        // --- K tile: [64 keys][128 dh perm] ---
        for (int i = tid; i < 64 * 32; i += 512) {
            const int r = i >> 5;
            const int col = (i & 31) << 2;
            const size_t rb = (size_t)(rowbase + k0 + r) * NQKV + Hq * Dh;
            float4 kv = *(const float4*)(qkv + rb + kh * Dh + col);
            const int pb = (col & ~7) | ((col >> 2) & 1);
            float* pk = Ks + r * AQSTR + pb;
            pk[0] = to_tf32(kv.x); pk[2] = to_tf32(kv.y);
            pk[4] = to_tf32(kv.z); pk[6] = to_tf32(kv.w);
        }
        // --- V tile transposed: Vt[dh][key perm]; lanes span keys ---
        for (int i = tid; i < 64 * 32; i += 512) {
            const int key  = i & 63;
            const int colg = (i >> 6) << 2;
            const size_t rb = (size_t)(rowbase + k0 + key) * NQKV
                              + Hq * Dh + HKV * Dh + kh * Dh;
            float4 vv = *(const float4*)(qkv + rb + colg);
            const int pk = KPERM(key);
            Vt[(colg + 0) * VTSTR + pk] = to_tf32(vv.x);
            Vt[(colg + 1) * VTSTR + pk] = to_tf32(vv.y);
            Vt[(colg + 2) * VTSTR + pk] = to_tf32(vv.z);
            Vt[(colg + 3) * VTSTR + pk] = to_tf32(vv.w);
        }
        __syncthreads();

        // --- QK^T: warp m16 x n32, k=128, LDS.64 fragments ---
        float sacc[4][4];
#pragma unroll
        for (int nt = 0; nt < 4; nt++)
#pragma unroll
            for (int r = 0; r < 4; r++) sacc[nt][r] = 0.f;

        const int rA = wm * 16 + gid;
#pragma unroll
        for (int kk = 0; kk < 16; kk++) {
            const int kcb = kk * 8;
            const float2 fa0 = *(const float2*)(Qs + rA * AQSTR + kcb + 2 * tig);
            const float2 fa1 = *(const float2*)(Qs + (rA + 8) * AQSTR + kcb + 2 * tig);
#pragma unroll
            for (int nt = 0; nt < 4; nt++) {
                const int rB = wn * 32 + nt * 8 + gid;
                const float2 fb = *(const float2*)(Ks + rB * AQSTR + kcb + 2 * tig);
                mma_tf32_16x8x8(sacc[nt][0], sacc[nt][1], sacc[nt][2], sacc[nt][3],
                                fa0.x, fa1.x, fa0.y, fa1.y, fb.x, fb.y);
            }
        }

        // --- scale + causal mask + write scores (perm positions) ---
        {
            const int r0 = rA;
            const int r1 = rA + 8;
            const int qr0 = q0 + r0, qr1 = q0 + r1;
#pragma unroll
            for (int nt = 0; nt < 4; nt++) {
                const int c0 = wn * 32 + nt * 8 + 2 * tig;
                const int c1 = c0 + 1;
                const int p0 = KPERM(c0);
                const int p1 = KPERM(c1);
                const int g0 = k0 + c0, g1 = k0 + c1;
                Ss[r0 * ASSTR + p0] = (g0 <= qr0) ? sacc[nt][0] * scale : -1e30f;
                Ss[r0 * ASSTR + p1] = (g1 <= qr0) ? sacc[nt][1] * scale : -1e30f;
                Ss[r1 * ASSTR + p0] = (g0 <= qr1) ? sacc[nt][2] * scale : -1e30f;
                Ss[r1 * ASSTR + p1] = (g1 <= qr1) ? sacc[nt][3] * scale : -1e30f;
            }
        }
        __syncthreads();

        // --- online softmax: 4 threads/row, 16 cols each (order-agnostic) ---
        {
            const int row = tid >> 2;
            const int part = tid & 3;
            float* sp = Ss + row * ASSTR + part * 16;
            float4 v0 = *(float4*)(sp);
            float4 v1 = *(float4*)(sp + 4);
            float4 v2 = *(float4*)(sp + 8);
            float4 v3 = *(float4*)(sp + 12);
            float mx = fmaxf(fmaxf(fmaxf(v0.x, v0.y), fmaxf(v0.z, v0.w)),
                             fmaxf(fmaxf(v1.x, v1.y), fmaxf(v1.z, v1.w)));
            mx = fmaxf(mx, fmaxf(fmaxf(fmaxf(v2.x, v2.y), fmaxf(v2.z, v2.w)),
                                 fmaxf(fmaxf(v3.x, v3.y), fmaxf(v3.z, v3.w))));
            mx = fmaxf(mx, __shfl_xor_sync(0xFFFFFFFFu, mx, 1));
            mx = fmaxf(mx, __shfl_xor_sync(0xFFFFFFFFu, mx, 2));
            const float mo = mrow[row];
            const float mn = fmaxf(mo, mx);
            const float alpha = __expf(mo - mn);
            v0.x = __expf(v0.x - mn); v0.y = __expf(v0.y - mn);
            v0.z = __expf(v0.z - mn); v0.w = __expf(v0.w - mn);
            v1.x = __expf(v1.x - mn); v1.y = __expf(v1.y - mn);
            v1.z = __expf(v1.z - mn); v1.w = __expf(v1.w - mn);
            v2.x = __expf(v2.x - mn); v2.y = __expf(v2.y - mn);
            v2.z = __expf(v2.z - mn); v2.w = __expf(v2.w - mn);
            v3.x = __expf(v3.x - mn); v3.y = __expf(v3.y - mn);
            v3.z = __expf(v3.z - mn); v3.w = __expf(v3.w - mn);
            float s = (v0.x + v0.y + v0.z + v0.w) + (v1.x + v1.y + v1.z + v1.w)
                    + (v2.x + v2.y + v2.z + v2.w) + (v3.x + v3.y + v3.z + v3.w);
            // store tf32-converted P (mma input); sum uses exact exps
            v0.x = to_tf32(v0.x); v0.y = to_tf32(v0.y);
            v0.z = to_tf32(v0.z); v0.w = to_tf32(v0.w);
            v1.x = to_tf32(v1.x); v1.y = to_tf32(v1.y);
            v1.z = to_tf32(v1.z); v1.w = to_tf32(v1.w);
            v2.x = to_tf32(v2.x); v2.y = to_tf32(v2.y);
            v2.z = to_tf32(v2.z); v2.w = to_tf32(v2.w);
            v3.x = to_tf32(v3.x); v3.y = to_tf32(v3.y);
            v3.z = to_tf32(v3.z); v3.w = to_tf32(v3.w);
            *(float4*)(sp)      = v0;
            *(float4*)(sp + 4)  = v1;
            *(float4*)(sp + 8)  = v2;
            *(float4*)(sp + 12) = v3;
            s += __shfl_xor_sync(0xFFFFFFFFu, s, 1);
            s += __shfl_xor_sync(0xFFFFFFFFu, s, 2);
            if (part == 0) {
                mrow[row] = mn;
                lrow[row] = lrow[row] * alpha + s;
                arow[row] = alpha;
            }
        }
        __syncthreads();

        // --- rescale O and P @ V (transposed V, LDS.64 fragments) ---
        {
            const float a0 = arow[rA];
            const float a1 = arow[rA + 8];
#pragma unroll
            for (int nt = 0; nt < 8; nt++) {
                oacc[nt][0] *= a0; oacc[nt][1] *= a0;
                oacc[nt][2] *= a1; oacc[nt][3] *= a1;
            }
#pragma unroll
            for (int ks = 0; ks < 8; ks++) {
                const int kcb = ks * 8;
                const float2 fp0 = *(const float2*)(Ss + rA * ASSTR + kcb + 2 * tig);
                const float2 fp1 = *(const float2*)(Ss + (rA + 8) * ASSTR + kcb + 2 * tig);
#pragma unroll
                for (int nt = 0; nt < 8; nt++) {
                    const int n = wn * 64 + nt * 8 + gid;
                    const float2 fb = *(const float2*)(Vt + n * VTSTR + kcb + 2 * tig);
                    mma_tf32_16x8x8(oacc[nt][0], oacc[nt][1], oacc[nt][2], oacc[nt][3],
                                    fp0.x, fp1.x, fp0.y, fp1.y, fb.x, fb.y);
                }
            }
        }
        __syncthreads();   // protect K/V/S before next iteration's overwrite
    }

    // --- normalize + write out ---
    {
        const int r0 = wm * 16 + gid;
        const int r1 = r0 + 8;
        const float inv0 = 1.0f / lrow[r0];
        const float inv1 = 1.0f / lrow[r1];
        const size_t ob0 = (size_t)(rowbase + q0 + r0) * HID + h * Dh;
        const size_t ob1 = (size_t)(rowbase + q0 + r1) * HID + h * Dh;
#pragma unroll
        for (int nt = 0; nt < 8; nt++) {
            const int col = wn * 64 + nt * 8 + 2 * tig;
            *(float2*)(out + ob0 + col) = make_float2(oacc[nt][0] * inv0, oacc[nt][1] * inv0);
            *(float2*)(out + ob1 + col) = make_float2(oacc[nt][2] * inv1, oacc[nt][3] * inv1);
        }
    }
}

// ---------------------------------------------------------------------------
// kernel_launch
// ---------------------------------------------------------------------------
extern "C" void kernel_launch(void* const* d_in, const int* in_sizes, int n_in,
                              void* d_out, int out_size) {
    const float* x    = (const float*)d_in[0];
    const float* cosb = (const float*)d_in[1];
    const float* sinb = (const float*)d_in[2];
    const float* kci  = (const float*)d_in[3];
    const float* vci  = (const float*)d_in[4];
    const int*   slot = (const int*)d_in[5];
    const float* Wqkv = (const float*)d_in[6];
    const float* bqkv = (const float*)d_in[7];
    const float* Wo   = (const float*)d_in[8];

    float* out = (float*)d_out;
    float* kc  = out + OUT_ELEMS;
    float* vc  = kc + CACHE_ELEMS;

    float* qkv;  cudaGetSymbolAddress((void**)&qkv,  g_qkv);
    float* attn; cudaGetSymbolAddress((void**)&attn, g_attn);

    cudaFuncSetAttribute(attn_mma_kernel,
                         cudaFuncAttributeMaxDynamicSharedMemorySize,
                         ATT2_SMEM_FLOATS * (int)sizeof(float));
    cudaFuncSetAttribute(gemm_mma_kernel,
                         cudaFuncAttributeMaxDynamicSharedMemorySize,
                         G_SMEM_FLOATS * (int)sizeof(float));

    // 1. seed caches with the input caches
    cudaMemcpyAsync(kc, kci, CACHE_ELEMS * sizeof(float), cudaMemcpyDeviceToDevice);
    cudaMemcpyAsync(vc, vci, CACHE_ELEMS * sizeof(float), cudaMemcpyDeviceToDevice);

    // 2. QKV projection (tf32 mma.sync)
    {
        dim3 grid(NQKV / 128, Tn / 128);
        gemm_mma_kernel<<<grid, 256, G_SMEM_FLOATS * sizeof(float)>>>(
            x, Wqkv, bqkv, qkv, Tn, NQKV, HID);
    }

    // 3. RoPE in place + cache scatter
    rope_scatter_kernel<<<Tn, 256>>>(qkv, cosb, sinb, slot, kc, vc);

    // 4. causal GQA flash attention (tensor cores)
    {
        dim3 grid(Sc / 128, Hq, Bc);
        attn_mma_kernel<<<grid, 512, ATT2_SMEM_FLOATS * sizeof(float)>>>(qkv, attn);
    }

    // 5. output projection (tf32 mma.sync)
    {
        dim3 grid(HID / 128, Tn / 128);
        gemm_mma_kernel<<<grid, 256, G_SMEM_FLOATS * sizeof(float)>>>(
            attn, Wo, nullptr, out, Tn, HID, HID);
    }
}

// round 6
// speedup vs baseline: 1.2903x; 1.2903x over previous
#include <cuda_runtime.h>
#include <cuda_bf16.h>
#include <cstdint>
#include <math.h>

// Problem constants
#define Hq    12
#define HKV   2
#define NG    6          // Hq / HKV
#define Dh    128
#define HID   1536
#define Bc    4
#define Sc    2048
#define Tn    (Bc*Sc)    // 8192 tokens
#define NQKV  2048       // Hq*Dh + 2*HKV*Dh
#define NSLOTS 16384
#define OUT_ELEMS   ((size_t)Tn*HID)          // 12582912
#define CACHE_ELEMS ((size_t)NSLOTS*HKV*Dh)   // 4194304

// Scratch (device globals; no runtime allocation allowed)
__device__ float g_qkv[(size_t)Tn * NQKV];    // 67 MB
__device__ float g_attn[(size_t)Tn * HID];    // 50 MB (tf32-rounded by attn)
__device__ float g_x [(size_t)Tn * HID];      // tf32-rounded x
__device__ float g_w1[(size_t)NQKV * HID];    // tf32-rounded Wqkv
__device__ float g_w2[(size_t)HID * HID];     // tf32-rounded Wo

// ===========================================================================
// Helpers (portable to plain sm_103 target)
// ===========================================================================
__device__ __forceinline__ float to_tf32(float x) {
    float y;
    asm("cvt.rna.tf32.f32 %0, %1;" : "=f"(y) : "f"(x));
    return y;
}

__device__ __forceinline__ uint32_t smem_u32(const void* p) {
    uint32_t a;
    asm("{ .reg .u64 t; cvta.to.shared.u64 t, %1; cvt.u32.u64 %0, t; }"
        : "=r"(a) : "l"(p));
    return a;
}

__device__ __forceinline__ void cp_async16(uint32_t saddr, const void* g) {
    asm volatile("cp.async.cg.shared.global [%0], [%1], 16;"
                 :: "r"(saddr), "l"(g) : "memory");
}

__device__ __forceinline__ void mma_tf32_16x8x8(
    float& d0, float& d1, float& d2, float& d3,
    float a0, float a1, float a2, float a3,
    float b0, float b1)
{
    uint32_t A0 = __float_as_uint(a0), A1 = __float_as_uint(a1);
    uint32_t A2 = __float_as_uint(a2), A3 = __float_as_uint(a3);
    uint32_t B0 = __float_as_uint(b0), B1 = __float_as_uint(b1);
    asm volatile(
        "mma.sync.aligned.m16n8k8.row.col.f32.tf32.tf32.f32 "
        "{%0,%1,%2,%3}, {%4,%5,%6,%7}, {%8,%9}, {%0,%1,%2,%3};"
        : "+f"(d0), "+f"(d1), "+f"(d2), "+f"(d3)
        : "r"(A0), "r"(A1), "r"(A2), "r"(A3), "r"(B0), "r"(B1));
}

// ---------------------------------------------------------------------------
// Pre-pass: round fp32 buffer to tf32 (rna) into scratch.
// ---------------------------------------------------------------------------
__global__ void tf32_round_kernel(const float* __restrict__ in,
                                  float* __restrict__ out, int n4) {
    const int i = blockIdx.x * blockDim.x + threadIdx.x;
    if (i < n4) {
        float4 v = ((const float4*)in)[i];
        v.x = to_tf32(v.x); v.y = to_tf32(v.y);
        v.z = to_tf32(v.z); v.w = to_tf32(v.w);
        ((float4*)out)[i] = v;
    }
}

// ===========================================================================
// TF32 tensor-core GEMM: C[M,N] = A[M,K] @ B[N,K]^T (+ bias[N])
// A, B must be tf32-pre-rounded. 128x128 tile, BK=32, 8 warps (2x4),
// cp.async double-buffered smem (no cvt / no staging in the hot loop).
// R4-validated fragment layout, stride 36.
// ===========================================================================
#define GSTR 36
#define GBUF (128 * GSTR)
#define G_SMEM_FLOATS (4 * GBUF)   // As[2] | Bs[2]

__global__ __launch_bounds__(256, 2) void gemm_mma_kernel(
    const float* __restrict__ A, const float* __restrict__ Bw,
    const float* __restrict__ bias, float* __restrict__ C,
    int M, int N, int K)
{
    extern __shared__ float smem[];
    const uint32_t sbase = smem_u32(smem);

    const int tid  = threadIdx.x;
    const int wid  = tid >> 5;
    const int lane = tid & 31;
    const int gid  = lane >> 2;
    const int tig  = lane & 3;

    const int m0 = blockIdx.y * 128;
    const int n0 = blockIdx.x * 128;
    const int wm0 = (wid >> 2) * 64;
    const int wn0 = (wid & 3) * 32;

    // per-thread load coords (4 rows x 16B each for A and B)
    const int r_ld  = tid >> 1;               // rows handled: r_ld, +128? no:
    // mapping: idx = tid + i*256 ; r = idx>>3 ; cg = (idx&7)<<2
    float acc[4][4][4];
#pragma unroll
    for (int mi = 0; mi < 4; mi++)
#pragma unroll
        for (int ni = 0; ni < 4; ni++)
#pragma unroll
            for (int r = 0; r < 4; r++) acc[mi][ni][r] = 0.f;
    (void)r_ld;

    const int nchunks = K >> 5;

#define GEMM_ISSUE(kc, buf) do {                                              \
    _Pragma("unroll")                                                         \
    for (int i = 0; i < 4; i++) {                                             \
        const int idx = tid + i * 256;                                        \
        const int r  = idx >> 3;                                              \
        const int cg = (idx & 7) << 2;                                        \
        cp_async16(sbase + (uint32_t)(((buf) * GBUF + r * GSTR + cg) * 4),    \
                   A + (size_t)(m0 + r) * K + (kc) + cg);                     \
        cp_async16(sbase + (uint32_t)(((2 + (buf)) * GBUF + r * GSTR + cg) * 4),\
                   Bw + (size_t)(n0 + r) * K + (kc) + cg);                    \
    }                                                                         \
    asm volatile("cp.async.commit_group;" ::: "memory");                      \
} while (0)

    GEMM_ISSUE(0, 0);

    int p = 0;
    for (int c = 0; c < nchunks; c++) {
        const bool more = (c + 1) < nchunks;
        if (more) {
            GEMM_ISSUE((c + 1) << 5, p ^ 1);
            asm volatile("cp.async.wait_group 1;" ::: "memory");
        } else {
            asm volatile("cp.async.wait_group 0;" ::: "memory");
        }
        __syncthreads();

        const float* Ab = smem + p * GBUF;
        const float* Bb = smem + (2 + p) * GBUF;
#pragma unroll
        for (int ks = 0; ks < 4; ks++) {
            const int kk = ks * 8;
            float afr[4][4];
#pragma unroll
            for (int mi = 0; mi < 4; mi++) {
                const int r = wm0 + mi * 16 + gid;
                const int cA = kk + tig;
                afr[mi][0] = Ab[r * GSTR + cA];
                afr[mi][1] = Ab[(r + 8) * GSTR + cA];
                afr[mi][2] = Ab[r * GSTR + cA + 4];
                afr[mi][3] = Ab[(r + 8) * GSTR + cA + 4];
            }
#pragma unroll
            for (int ni = 0; ni < 4; ni++) {
                const int rB = wn0 + ni * 8 + gid;
                const int cB = kk + tig;
                const float b0 = Bb[rB * GSTR + cB];
                const float b1 = Bb[rB * GSTR + cB + 4];
#pragma unroll
                for (int mi = 0; mi < 4; mi++) {
                    mma_tf32_16x8x8(acc[mi][ni][0], acc[mi][ni][1],
                                    acc[mi][ni][2], acc[mi][ni][3],
                                    afr[mi][0], afr[mi][1], afr[mi][2], afr[mi][3],
                                    b0, b1);
                }
            }
        }
        __syncthreads();   // compute done before buffer p is re-filled
        p ^= 1;
    }

#pragma unroll
    for (int mi = 0; mi < 4; mi++) {
        const int row = m0 + wm0 + mi * 16 + gid;
#pragma unroll
        for (int ni = 0; ni < 4; ni++) {
            const int col = n0 + wn0 + ni * 8 + 2 * tig;
            float b0 = 0.f, b1 = 0.f;
            if (bias) { b0 = bias[col]; b1 = bias[col + 1]; }
            float2 v0 = make_float2(acc[mi][ni][0] + b0, acc[mi][ni][1] + b1);
            float2 v1 = make_float2(acc[mi][ni][2] + b0, acc[mi][ni][3] + b1);
            *(float2*)(C + (size_t)row * N + col)       = v0;
            *(float2*)(C + (size_t)(row + 8) * N + col) = v1;
        }
    }
}

// ---------------------------------------------------------------------------
// RoPE (in place on g_qkv) + scatter EXACT rotated k and raw v to caches,
// and round q/k/v in qkv to tf32 (so attention loads need no cvt).
// ---------------------------------------------------------------------------
__global__ void rope_scatter_kernel(float* __restrict__ qkv,
                                    const float* __restrict__ cosb,
                                    const float* __restrict__ sinb,
                                    const int* __restrict__ slot,
                                    float* __restrict__ kc,
                                    float* __restrict__ vc) {
    const int r = blockIdx.x;
    float* row = qkv + (size_t)r * NQKV;
    const float* cr = cosb + (size_t)r * Dh;
    const float* sr = sinb + (size_t)r * Dh;
    const int s = slot[r];

    for (int idx = threadIdx.x; idx < 14 * 64; idx += blockDim.x) {
        const int head = idx >> 6;
        const int d = idx & 63;
        float* hp = row + head * Dh;
        const float x1 = hp[d], x2 = hp[d + 64];
        const float c1 = cr[d], s1 = sr[d];
        const float c2 = cr[d + 64], s2 = sr[d + 64];
        const float o1 = x1 * c1 - x2 * s1;
        const float o2 = x2 * c2 + x1 * s2;
        hp[d]      = to_tf32(o1);
        hp[d + 64] = to_tf32(o2);
        if (head >= Hq) {
            const int kh = head - Hq;
            float* kdst = kc + ((size_t)s * HKV + kh) * Dh;
            kdst[d]      = o1;        // cache keeps exact values
            kdst[d + 64] = o2;
        }
    }
    for (int idx = threadIdx.x; idx < HKV * Dh; idx += blockDim.x) {
        const float v = row[Hq * Dh + HKV * Dh + idx];
        vc[(size_t)s * (HKV * Dh) + idx] = v;         // exact
        row[Hq * Dh + HKV * Dh + idx] = to_tf32(v);   // rounded for PV mma
    }
}

// ===========================================================================
// Tensor-core causal GQA flash attention (tf32 mma.sync) — R4 layout.
// CTA: 128-query tile per (head, batch). 512 threads = 16 warps (8M x 2N).
//   QK: warp m16 x n32, k=128.   PV: warp m16 x n64, k=64.
// qkv is tf32-pre-rounded; output rounded to tf32 for the out-projection.
// ===========================================================================
#define AQSTR 132
#define AKSTR 132
#define AVSTR 136
#define ASSTR 68
#define ATT_Q_FL   (128 * AQSTR)
#define ATT_K_FL   (64 * AKSTR)
#define ATT_V_FL   (64 * AVSTR)
#define ATT_S_FL   (128 * ASSTR)
#define ATT2_SMEM_FLOATS (ATT_Q_FL + ATT_K_FL + ATT_V_FL + ATT_S_FL + 3 * 128)

__global__ __launch_bounds__(512) void attn_mma_kernel(
    const float* __restrict__ qkv, float* __restrict__ out)
{
    extern __shared__ float sm[];
    float* Qs = sm;
    float* Ks = Qs + ATT_Q_FL;
    float* Vs = Ks + ATT_K_FL;
    float* Ss = Vs + ATT_V_FL;
    float* mrow = Ss + ATT_S_FL;
    float* lrow = mrow + 128;
    float* arow = lrow + 128;

    const int qt = (gridDim.x - 1) - blockIdx.x;   // heavy tiles first
    const int h = blockIdx.y, b = blockIdx.z;
    const int kh = h / NG;
    const int tid = threadIdx.x;
    const int wid = tid >> 5;
    const int lane = tid & 31;
    const int gid = lane >> 2;
    const int tig = lane & 3;
    const int wm = wid >> 1;
    const int wn = wid & 1;
    const int q0 = qt * 128;
    const int rowbase = b * Sc;
    const float scale = 0.08838834764831845f;   // 1/sqrt(128)

    // --- load Q tile (already tf32-rounded) ---
    for (int i = tid; i < 128 * 32; i += 512) {
        const int r = i >> 5;
        const int col = (i & 31) << 2;
        float4 v = *(const float4*)(qkv + (size_t)(rowbase + q0 + r) * NQKV + h * Dh + col);
        *(float4*)(Qs + r * AQSTR + col) = v;
    }
    if (tid < 128) { mrow[tid] = -1e30f; lrow[tid] = 0.f; }

    float oacc[8][4];
#pragma unroll
    for (int nt = 0; nt < 8; nt++)
#pragma unroll
        for (int r = 0; r < 4; r++) oacc[nt][r] = 0.f;

    __syncthreads();

    const int nkt = 2 * qt + 2;
    for (int kt = 0; kt < nkt; kt++) {
        const int k0 = kt * 64;

        // --- load K/V tile (already tf32-rounded) ---
        for (int i = tid; i < 64 * 32; i += 512) {
            const int r = i >> 5;
            const int col = (i & 31) << 2;
            const size_t rb = (size_t)(rowbase + k0 + r) * NQKV + Hq * Dh;
            *(float4*)(Ks + r * AKSTR + col) =
                *(const float4*)(qkv + rb + kh * Dh + col);
            *(float4*)(Vs + r * AVSTR + col) =
                *(const float4*)(qkv + rb + HKV * Dh + kh * Dh + col);
        }
        __syncthreads();

        // --- QK^T: warp m16 x n32, k=128 ---
        float sacc[4][4];
#pragma unroll
        for (int nt = 0; nt < 4; nt++)
#pragma unroll
            for (int r = 0; r < 4; r++) sacc[nt][r] = 0.f;

#pragma unroll
        for (int kk = 0; kk < 16; kk++) {
            const int kc = kk * 8;
            const int rA = wm * 16 + gid;
            const float a0 = Qs[rA * AQSTR + kc + tig];
            const float a1 = Qs[(rA + 8) * AQSTR + kc + tig];
            const float a2 = Qs[rA * AQSTR + kc + tig + 4];
            const float a3 = Qs[(rA + 8) * AQSTR + kc + tig + 4];
#pragma unroll
            for (int nt = 0; nt < 4; nt++) {
                const int rB = wn * 32 + nt * 8 + gid;
                const float b0 = Ks[rB * AKSTR + kc + tig];
                const float b1 = Ks[rB * AKSTR + kc + tig + 4];
                mma_tf32_16x8x8(sacc[nt][0], sacc[nt][1], sacc[nt][2], sacc[nt][3],
                                a0, a1, a2, a3, b0, b1);
            }
        }

        // --- scale + causal mask + write scores ---
        {
            const int r0 = wm * 16 + gid;
            const int r1 = r0 + 8;
            const int qr0 = q0 + r0, qr1 = q0 + r1;
#pragma unroll
            for (int nt = 0; nt < 4; nt++) {
                const int col = wn * 32 + nt * 8 + 2 * tig;
                const int gc = k0 + col;
                Ss[r0 * ASSTR + col]     = (gc     <= qr0) ? sacc[nt][0] * scale : -1e30f;
                Ss[r0 * ASSTR + col + 1] = (gc + 1 <= qr0) ? sacc[nt][1] * scale : -1e30f;
                Ss[r1 * ASSTR + col]     = (gc     <= qr1) ? sacc[nt][2] * scale : -1e30f;
                Ss[r1 * ASSTR + col + 1] = (gc + 1 <= qr1) ? sacc[nt][3] * scale : -1e30f;
            }
        }
        __syncthreads();

        // --- online softmax: 4 threads/row, 16 cols each; store tf32 P ---
        {
            const int row = tid >> 2;
            const int part = tid & 3;
            float* sp = Ss + row * ASSTR + part * 16;
            float4 v0 = *(float4*)(sp);
            float4 v1 = *(float4*)(sp + 4);
            float4 v2 = *(float4*)(sp + 8);
            float4 v3 = *(float4*)(sp + 12);
            float mx = fmaxf(fmaxf(fmaxf(v0.x, v0.y), fmaxf(v0.z, v0.w)),
                             fmaxf(fmaxf(v1.x, v1.y), fmaxf(v1.z, v1.w)));
            mx = fmaxf(mx, fmaxf(fmaxf(fmaxf(v2.x, v2.y), fmaxf(v2.z, v2.w)),
                                 fmaxf(fmaxf(v3.x, v3.y), fmaxf(v3.z, v3.w))));
            mx = fmaxf(mx, __shfl_xor_sync(0xFFFFFFFFu, mx, 1));
            mx = fmaxf(mx, __shfl_xor_sync(0xFFFFFFFFu, mx, 2));
            const float mo = mrow[row];
            const float mn = fmaxf(mo, mx);
            const float alpha = __expf(mo - mn);
            v0.x = __expf(v0.x - mn); v0.y = __expf(v0.y - mn);
            v0.z = __expf(v0.z - mn); v0.w = __expf(v0.w - mn);
            v1.x = __expf(v1.x - mn); v1.y = __expf(v1.y - mn);
            v1.z = __expf(v1.z - mn); v1.w = __expf(v1.w - mn);
            v2.x = __expf(v2.x - mn); v2.y = __expf(v2.y - mn);
            v2.z = __expf(v2.z - mn); v2.w = __expf(v2.w - mn);
            v3.x = __expf(v3.x - mn); v3.y = __expf(v3.y - mn);
            v3.z = __expf(v3.z - mn); v3.w = __expf(v3.w - mn);
            float s = (v0.x + v0.y + v0.z + v0.w) + (v1.x + v1.y + v1.z + v1.w)
                    + (v2.x + v2.y + v2.z + v2.w) + (v3.x + v3.y + v3.z + v3.w);
            v0.x = to_tf32(v0.x); v0.y = to_tf32(v0.y);
            v0.z = to_tf32(v0.z); v0.w = to_tf32(v0.w);
            v1.x = to_tf32(v1.x); v1.y = to_tf32(v1.y);
            v1.z = to_tf32(v1.z); v1.w = to_tf32(v1.w);
            v2.x = to_tf32(v2.x); v2.y = to_tf32(v2.y);
            v2.z = to_tf32(v2.z); v2.w = to_tf32(v2.w);
            v3.x = to_tf32(v3.x); v3.y = to_tf32(v3.y);
            v3.z = to_tf32(v3.z); v3.w = to_tf32(v3.w);
            *(float4*)(sp)      = v0;
            *(float4*)(sp + 4)  = v1;
            *(float4*)(sp + 8)  = v2;
            *(float4*)(sp + 12) = v3;
            s += __shfl_xor_sync(0xFFFFFFFFu, s, 1);
            s += __shfl_xor_sync(0xFFFFFFFFu, s, 2);
            if (part == 0) {
                mrow[row] = mn;
                lrow[row] = lrow[row] * alpha + s;
                arow[row] = alpha;
            }
        }
        __syncthreads();

        // --- rescale O accumulators and P @ V ---
        {
            const float a0 = arow[wm * 16 + gid];
            const float a1 = arow[wm * 16 + gid + 8];
#pragma unroll
            for (int nt = 0; nt < 8; nt++) {
                oacc[nt][0] *= a0; oacc[nt][1] *= a0;
                oacc[nt][2] *= a1; oacc[nt][3] *= a1;
            }
#pragma unroll
            for (int ks = 0; ks < 8; ks++) {
                const int kc = ks * 8;
                const int rA = wm * 16 + gid;
                const float a0f = Ss[rA * ASSTR + kc + tig];
                const float a1f = Ss[(rA + 8) * ASSTR + kc + tig];
                const float a2f = Ss[rA * ASSTR + kc + tig + 4];
                const float a3f = Ss[(rA + 8) * ASSTR + kc + tig + 4];
#pragma unroll
                for (int nt = 0; nt < 8; nt++) {
                    const int n0 = wn * 64 + nt * 8;
                    const float b0 = Vs[(kc + tig) * AVSTR + n0 + gid];
                    const float b1 = Vs[(kc + tig + 4) * AVSTR + n0 + gid];
                    mma_tf32_16x8x8(oacc[nt][0], oacc[nt][1], oacc[nt][2], oacc[nt][3],
                                    a0f, a1f, a2f, a3f, b0, b1);
                }
            }
        }
        __syncthreads();
    }

    // --- normalize + write out (tf32-rounded for the out-projection) ---
    {
        const int r0 = wm * 16 + gid;
        const int r1 = r0 + 8;
        const float inv0 = 1.0f / lrow[r0];
        const float inv1 = 1.0f / lrow[r1];
        const size_t ob0 = (size_t)(rowbase + q0 + r0) * HID + h * Dh;
        const size_t ob1 = (size_t)(rowbase + q0 + r1) * HID + h * Dh;
#pragma unroll
        for (int nt = 0; nt < 8; nt++) {
            const int col = wn * 64 + nt * 8 + 2 * tig;
            *(float2*)(out + ob0 + col) =
                make_float2(to_tf32(oacc[nt][0] * inv0), to_tf32(oacc[nt][1] * inv0));
            *(float2*)(out + ob1 + col) =
                make_float2(to_tf32(oacc[nt][2] * inv1), to_tf32(oacc[nt][3] * inv1));
        }
    }
}

// ---------------------------------------------------------------------------
// kernel_launch
// ---------------------------------------------------------------------------
extern "C" void kernel_launch(void* const* d_in, const int* in_sizes, int n_in,
                              void* d_out, int out_size) {
    const float* x    = (const float*)d_in[0];
    const float* cosb = (const float*)d_in[1];
    const float* sinb = (const float*)d_in[2];
    const float* kci  = (const float*)d_in[3];
    const float* vci  = (const float*)d_in[4];
    const int*   slot = (const int*)d_in[5];
    const float* Wqkv = (const float*)d_in[6];
    const float* bqkv = (const float*)d_in[7];
    const float* Wo   = (const float*)d_in[8];

    float* out = (float*)d_out;
    float* kc  = out + OUT_ELEMS;
    float* vc  = kc + CACHE_ELEMS;

    float* qkv;  cudaGetSymbolAddress((void**)&qkv,  g_qkv);
    float* attn; cudaGetSymbolAddress((void**)&attn, g_attn);
    float* xe;   cudaGetSymbolAddress((void**)&xe,   g_x);
    float* w1e;  cudaGetSymbolAddress((void**)&w1e,  g_w1);
    float* w2e;  cudaGetSymbolAddress((void**)&w2e,  g_w2);

    cudaFuncSetAttribute(attn_mma_kernel,
                         cudaFuncAttributeMaxDynamicSharedMemorySize,
                         ATT2_SMEM_FLOATS * (int)sizeof(float));
    cudaFuncSetAttribute(gemm_mma_kernel,
                         cudaFuncAttributeMaxDynamicSharedMemorySize,
                         G_SMEM_FLOATS * (int)sizeof(float));

    // 1. seed caches with the input caches
    cudaMemcpyAsync(kc, kci, CACHE_ELEMS * sizeof(float), cudaMemcpyDeviceToDevice);
    cudaMemcpyAsync(vc, vci, CACHE_ELEMS * sizeof(float), cudaMemcpyDeviceToDevice);

    // 2. tf32 pre-rounding of GEMM operands
    tf32_round_kernel<<<(Tn * HID / 4 + 255) / 256, 256>>>(x,    xe,  Tn * HID / 4);
    tf32_round_kernel<<<(NQKV * HID / 4 + 255) / 256, 256>>>(Wqkv, w1e, NQKV * HID / 4);
    tf32_round_kernel<<<(HID * HID / 4 + 255) / 256, 256>>>(Wo,   w2e, HID * HID / 4);

    // 3. QKV projection (cp.async tf32 mma GEMM)
    {
        dim3 grid(NQKV / 128, Tn / 128);
        gemm_mma_kernel<<<grid, 256, G_SMEM_FLOATS * sizeof(float)>>>(
            xe, w1e, bqkv, qkv, Tn, NQKV, HID);
    }

    // 4. RoPE in place (+tf32 rounding) + exact cache scatter
    rope_scatter_kernel<<<Tn, 256>>>(qkv, cosb, sinb, slot, kc, vc);

    // 5. causal GQA flash attention (tensor cores)
    {
        dim3 grid(Sc / 128, Hq, Bc);
        attn_mma_kernel<<<grid, 512, ATT2_SMEM_FLOATS * sizeof(float)>>>(qkv, attn);
    }

    // 6. output projection (cp.async tf32 mma GEMM)
    {
        dim3 grid(HID / 128, Tn / 128);
        gemm_mma_kernel<<<grid, 256, G_SMEM_FLOATS * sizeof(float)>>>(
            attn, w2e, nullptr, out, Tn, HID, HID);
    }
}

// round 7
// speedup vs baseline: 1.3742x; 1.0650x over previous
#include <cuda_runtime.h>
#include <cuda_bf16.h>
#include <cstdint>
#include <math.h>

// Problem constants
#define Hq    12
#define HKV   2
#define NG    6          // Hq / HKV
#define Dh    128
#define HID   1536
#define Bc    4
#define Sc    2048
#define Tn    (Bc*Sc)    // 8192 tokens
#define NQKV  2048       // Hq*Dh + 2*HKV*Dh
#define NSLOTS 16384
#define OUT_ELEMS   ((size_t)Tn*HID)          // 12582912
#define CACHE_ELEMS ((size_t)NSLOTS*HKV*Dh)   // 4194304

// Scratch (device globals; no runtime allocation allowed)
__device__ float g_qkv[(size_t)Tn * NQKV];    // 67 MB
__device__ float g_attn[(size_t)Tn * HID];    // 50 MB (tf32-rounded by attn)
__device__ float g_x [(size_t)Tn * HID];      // tf32-rounded x
__device__ float g_w1[(size_t)NQKV * HID];    // tf32-rounded Wqkv
__device__ float g_w2[(size_t)HID * HID];     // tf32-rounded Wo

// ===========================================================================
// Helpers (portable to plain sm_103 target)
// ===========================================================================
__device__ __forceinline__ float to_tf32(float x) {
    float y;
    asm("cvt.rna.tf32.f32 %0, %1;" : "=f"(y) : "f"(x));
    return y;
}

__device__ __forceinline__ uint32_t smem_u32(const void* p) {
    uint32_t a;
    asm("{ .reg .u64 t; cvta.to.shared.u64 t, %1; cvt.u32.u64 %0, t; }"
        : "=r"(a) : "l"(p));
    return a;
}

__device__ __forceinline__ void cp_async16(uint32_t saddr, const void* g) {
    asm volatile("cp.async.cg.shared.global [%0], [%1], 16;"
                 :: "r"(saddr), "l"(g) : "memory");
}

__device__ __forceinline__ void mma_tf32_16x8x8(
    float& d0, float& d1, float& d2, float& d3,
    float a0, float a1, float a2, float a3,
    float b0, float b1)
{
    uint32_t A0 = __float_as_uint(a0), A1 = __float_as_uint(a1);
    uint32_t A2 = __float_as_uint(a2), A3 = __float_as_uint(a3);
    uint32_t B0 = __float_as_uint(b0), B1 = __float_as_uint(b1);
    asm volatile(
        "mma.sync.aligned.m16n8k8.row.col.f32.tf32.tf32.f32 "
        "{%0,%1,%2,%3}, {%4,%5,%6,%7}, {%8,%9}, {%0,%1,%2,%3};"
        : "+f"(d0), "+f"(d1), "+f"(d2), "+f"(d3)
        : "r"(A0), "r"(A1), "r"(A2), "r"(A3), "r"(B0), "r"(B1));
}

// ---------------------------------------------------------------------------
// Pre-pass: round fp32 buffer to tf32 (rna) into scratch.
// ---------------------------------------------------------------------------
__global__ void tf32_round_kernel(const float* __restrict__ in,
                                  float* __restrict__ out, int n4) {
    const int i = blockIdx.x * blockDim.x + threadIdx.x;
    if (i < n4) {
        float4 v = ((const float4*)in)[i];
        v.x = to_tf32(v.x); v.y = to_tf32(v.y);
        v.z = to_tf32(v.z); v.w = to_tf32(v.w);
        ((float4*)out)[i] = v;
    }
}

// ===========================================================================
// TF32 tensor-core GEMM: C[M,N] = A[M,K] @ B[N,K]^T (+ bias[N])
// (R6-validated: cp.async double-buffered, stride-36 fragment layout)
// ===========================================================================
#define GSTR 36
#define GBUF (128 * GSTR)
#define G_SMEM_FLOATS (4 * GBUF)   // As[2] | Bs[2]

__global__ __launch_bounds__(256, 2) void gemm_mma_kernel(
    const float* __restrict__ A, const float* __restrict__ Bw,
    const float* __restrict__ bias, float* __restrict__ C,
    int M, int N, int K)
{
    extern __shared__ float smem[];
    const uint32_t sbase = smem_u32(smem);

    const int tid  = threadIdx.x;
    const int wid  = tid >> 5;
    const int lane = tid & 31;
    const int gid  = lane >> 2;
    const int tig  = lane & 3;

    const int m0 = blockIdx.y * 128;
    const int n0 = blockIdx.x * 128;
    const int wm0 = (wid >> 2) * 64;
    const int wn0 = (wid & 3) * 32;

    float acc[4][4][4];
#pragma unroll
    for (int mi = 0; mi < 4; mi++)
#pragma unroll
        for (int ni = 0; ni < 4; ni++)
#pragma unroll
            for (int r = 0; r < 4; r++) acc[mi][ni][r] = 0.f;

    const int nchunks = K >> 5;

#define GEMM_ISSUE(kc, buf) do {                                              \
    _Pragma("unroll")                                                         \
    for (int i = 0; i < 4; i++) {                                             \
        const int idx = tid + i * 256;                                        \
        const int r  = idx >> 3;                                              \
        const int cg = (idx & 7) << 2;                                        \
        cp_async16(sbase + (uint32_t)(((buf) * GBUF + r * GSTR + cg) * 4),    \
                   A + (size_t)(m0 + r) * K + (kc) + cg);                     \
        cp_async16(sbase + (uint32_t)(((2 + (buf)) * GBUF + r * GSTR + cg) * 4),\
                   Bw + (size_t)(n0 + r) * K + (kc) + cg);                    \
    }                                                                         \
    asm volatile("cp.async.commit_group;" ::: "memory");                      \
} while (0)

    GEMM_ISSUE(0, 0);

    int p = 0;
    for (int c = 0; c < nchunks; c++) {
        const bool more = (c + 1) < nchunks;
        if (more) {
            GEMM_ISSUE((c + 1) << 5, p ^ 1);
            asm volatile("cp.async.wait_group 1;" ::: "memory");
        } else {
            asm volatile("cp.async.wait_group 0;" ::: "memory");
        }
        __syncthreads();

        const float* Ab = smem + p * GBUF;
        const float* Bb = smem + (2 + p) * GBUF;
#pragma unroll
        for (int ks = 0; ks < 4; ks++) {
            const int kk = ks * 8;
            float afr[4][4];
#pragma unroll
            for (int mi = 0; mi < 4; mi++) {
                const int r = wm0 + mi * 16 + gid;
                const int cA = kk + tig;
                afr[mi][0] = Ab[r * GSTR + cA];
                afr[mi][1] = Ab[(r + 8) * GSTR + cA];
                afr[mi][2] = Ab[r * GSTR + cA + 4];
                afr[mi][3] = Ab[(r + 8) * GSTR + cA + 4];
            }
#pragma unroll
            for (int ni = 0; ni < 4; ni++) {
                const int rB = wn0 + ni * 8 + gid;
                const int cB = kk + tig;
                const float b0 = Bb[rB * GSTR + cB];
                const float b1 = Bb[rB * GSTR + cB + 4];
#pragma unroll
                for (int mi = 0; mi < 4; mi++) {
                    mma_tf32_16x8x8(acc[mi][ni][0], acc[mi][ni][1],
                                    acc[mi][ni][2], acc[mi][ni][3],
                                    afr[mi][0], afr[mi][1], afr[mi][2], afr[mi][3],
                                    b0, b1);
                }
            }
        }
        __syncthreads();
        p ^= 1;
    }

#pragma unroll
    for (int mi = 0; mi < 4; mi++) {
        const int row = m0 + wm0 + mi * 16 + gid;
#pragma unroll
        for (int ni = 0; ni < 4; ni++) {
            const int col = n0 + wn0 + ni * 8 + 2 * tig;
            float b0 = 0.f, b1 = 0.f;
            if (bias) { b0 = bias[col]; b1 = bias[col + 1]; }
            float2 v0 = make_float2(acc[mi][ni][0] + b0, acc[mi][ni][1] + b1);
            float2 v1 = make_float2(acc[mi][ni][2] + b0, acc[mi][ni][3] + b1);
            *(float2*)(C + (size_t)row * N + col)       = v0;
            *(float2*)(C + (size_t)(row + 8) * N + col) = v1;
        }
    }
}

// ---------------------------------------------------------------------------
// RoPE (in place on g_qkv) + scatter EXACT rotated k and raw v to caches,
// and round q/k/v in qkv to tf32 (so attention loads need no cvt).
// ---------------------------------------------------------------------------
__global__ void rope_scatter_kernel(float* __restrict__ qkv,
                                    const float* __restrict__ cosb,
                                    const float* __restrict__ sinb,
                                    const int* __restrict__ slot,
                                    float* __restrict__ kc,
                                    float* __restrict__ vc) {
    const int r = blockIdx.x;
    float* row = qkv + (size_t)r * NQKV;
    const float* cr = cosb + (size_t)r * Dh;
    const float* sr = sinb + (size_t)r * Dh;
    const int s = slot[r];

    for (int idx = threadIdx.x; idx < 14 * 64; idx += blockDim.x) {
        const int head = idx >> 6;
        const int d = idx & 63;
        float* hp = row + head * Dh;
        const float x1 = hp[d], x2 = hp[d + 64];
        const float c1 = cr[d], s1 = sr[d];
        const float c2 = cr[d + 64], s2 = sr[d + 64];
        const float o1 = x1 * c1 - x2 * s1;
        const float o2 = x2 * c2 + x1 * s2;
        hp[d]      = to_tf32(o1);
        hp[d + 64] = to_tf32(o2);
        if (head >= Hq) {
            const int kh = head - Hq;
            float* kdst = kc + ((size_t)s * HKV + kh) * Dh;
            kdst[d]      = o1;        // cache keeps exact values
            kdst[d + 64] = o2;
        }
    }
    for (int idx = threadIdx.x; idx < HKV * Dh; idx += blockDim.x) {
        const float v = row[Hq * Dh + HKV * Dh + idx];
        vc[(size_t)s * (HKV * Dh) + idx] = v;         // exact
        row[Hq * Dh + HKV * Dh + idx] = to_tf32(v);   // rounded for PV mma
    }
}

// ===========================================================================
// Tensor-core causal GQA flash attention (tf32 mma.sync), cp.async-pipelined.
// CTA: 128-query tile per (head, batch). 512 threads = 16 warps (8M x 2N).
//   K double-buffered (prefetch kt+1 during kt); V single buffer, early-issued
//   at iteration top and waited only after softmax.
// ===========================================================================
#define AQSTR 132
#define AKSTR 132
#define AVSTR 136
#define ASSTR 68
#define ATT_Q_FL   (128 * AQSTR)
#define ATT_K_FL   (64 * AKSTR)
#define ATT_V_FL   (64 * AVSTR)
#define ATT_S_FL   (128 * ASSTR)
#define ATT2_SMEM_FLOATS (ATT_Q_FL + 2 * ATT_K_FL + ATT_V_FL + ATT_S_FL + 3 * 128)

__global__ __launch_bounds__(512) void attn_mma_kernel(
    const float* __restrict__ qkv, float* __restrict__ out)
{
    extern __shared__ float sm[];
    float* Qs = sm;
    float* Ks0 = Qs + ATT_Q_FL;                 // [2][64][AKSTR]
    float* Vs  = Ks0 + 2 * ATT_K_FL;
    float* Ss  = Vs + ATT_V_FL;
    float* mrow = Ss + ATT_S_FL;
    float* lrow = mrow + 128;
    float* arow = lrow + 128;

    const uint32_t sbase = smem_u32(sm);
    const uint32_t ks_s0 = sbase + (uint32_t)(ATT_Q_FL * 4);
    const uint32_t vs_s  = sbase + (uint32_t)((ATT_Q_FL + 2 * ATT_K_FL) * 4);

    const int qt = (gridDim.x - 1) - blockIdx.x;   // heavy tiles first
    const int h = blockIdx.y, b = blockIdx.z;
    const int kh = h / NG;
    const int tid = threadIdx.x;
    const int wid = tid >> 5;
    const int lane = tid & 31;
    const int gid = lane >> 2;
    const int tig = lane & 3;
    const int wm = wid >> 1;
    const int wn = wid & 1;
    const int q0 = qt * 128;
    const int rowbase = b * Sc;
    const float scale = 0.08838834764831845f;   // 1/sqrt(128)

#define ATT_ISSUE_K(kt_, buf_) do {                                           \
    const uint32_t kb_ = ks_s0 + (uint32_t)((buf_) * ATT_K_FL * 4);           \
    for (int i_ = tid; i_ < 64 * 32; i_ += 512) {                             \
        const int r_ = i_ >> 5; const int c_ = (i_ & 31) << 2;                \
        cp_async16(kb_ + (uint32_t)((r_ * AKSTR + c_) * 4),                   \
                   qkv + (size_t)(rowbase + (kt_) * 64 + r_) * NQKV           \
                       + Hq * Dh + kh * Dh + c_);                             \
    }                                                                         \
} while (0)

#define ATT_ISSUE_V(kt_) do {                                                 \
    for (int i_ = tid; i_ < 64 * 32; i_ += 512) {                             \
        const int r_ = i_ >> 5; const int c_ = (i_ & 31) << 2;                \
        cp_async16(vs_s + (uint32_t)((r_ * AVSTR + c_) * 4),                  \
                   qkv + (size_t)(rowbase + (kt_) * 64 + r_) * NQKV           \
                       + Hq * Dh + HKV * Dh + kh * Dh + c_);                  \
    }                                                                         \
} while (0)

    // --- prologue: prefetch K tile 0, load Q, init stats ---
    ATT_ISSUE_K(0, 0);
    asm volatile("cp.async.commit_group;" ::: "memory");

    for (int i = tid; i < 128 * 32; i += 512) {
        const int r = i >> 5;
        const int col = (i & 31) << 2;
        float4 v = *(const float4*)(qkv + (size_t)(rowbase + q0 + r) * NQKV + h * Dh + col);
        *(float4*)(Qs + r * AQSTR + col) = v;
    }
    if (tid < 128) { mrow[tid] = -1e30f; lrow[tid] = 0.f; }

    float oacc[8][4];
#pragma unroll
    for (int nt = 0; nt < 8; nt++)
#pragma unroll
        for (int r = 0; r < 4; r++) oacc[nt][r] = 0.f;

    asm volatile("cp.async.wait_group 0;" ::: "memory");
    __syncthreads();    // K0 + Q + stats visible

    const int nkt = 2 * qt + 2;
    for (int kt = 0; kt < nkt; kt++) {
        const int k0 = kt * 64;
        const int buf = kt & 1;

        // --- issue V(kt) and prefetch K(kt+1); one commit group ---
        ATT_ISSUE_V(kt);
        if (kt + 1 < nkt) ATT_ISSUE_K(kt + 1, buf ^ 1);
        asm volatile("cp.async.commit_group;" ::: "memory");

        // --- QK^T from Ks[buf]: warp m16 x n32, k=128 ---
        const float* Kb = Ks0 + buf * ATT_K_FL;
        float sacc[4][4];
#pragma unroll
        for (int nt = 0; nt < 4; nt++)
#pragma unroll
            for (int r = 0; r < 4; r++) sacc[nt][r] = 0.f;

#pragma unroll
        for (int kk = 0; kk < 16; kk++) {
            const int kc = kk * 8;
            const int rA = wm * 16 + gid;
            const float a0 = Qs[rA * AQSTR + kc + tig];
            const float a1 = Qs[(rA + 8) * AQSTR + kc + tig];
            const float a2 = Qs[rA * AQSTR + kc + tig + 4];
            const float a3 = Qs[(rA + 8) * AQSTR + kc + tig + 4];
#pragma unroll
            for (int nt = 0; nt < 4; nt++) {
                const int rB = wn * 32 + nt * 8 + gid;
                const float b0 = Kb[rB * AKSTR + kc + tig];
                const float b1 = Kb[rB * AKSTR + kc + tig + 4];
                mma_tf32_16x8x8(sacc[nt][0], sacc[nt][1], sacc[nt][2], sacc[nt][3],
                                a0, a1, a2, a3, b0, b1);
            }
        }

        // --- scale + causal mask + write scores ---
        {
            const int r0 = wm * 16 + gid;
            const int r1 = r0 + 8;
            const int qr0 = q0 + r0, qr1 = q0 + r1;
#pragma unroll
            for (int nt = 0; nt < 4; nt++) {
                const int col = wn * 32 + nt * 8 + 2 * tig;
                const int gc = k0 + col;
                Ss[r0 * ASSTR + col]     = (gc     <= qr0) ? sacc[nt][0] * scale : -1e30f;
                Ss[r0 * ASSTR + col + 1] = (gc + 1 <= qr0) ? sacc[nt][1] * scale : -1e30f;
                Ss[r1 * ASSTR + col]     = (gc     <= qr1) ? sacc[nt][2] * scale : -1e30f;
                Ss[r1 * ASSTR + col + 1] = (gc + 1 <= qr1) ? sacc[nt][3] * scale : -1e30f;
            }
        }
        __syncthreads();

        // --- online softmax: 4 threads/row, 16 cols each; store tf32 P ---
        {
            const int row = tid >> 2;
            const int part = tid & 3;
            float* sp = Ss + row * ASSTR + part * 16;
            float4 v0 = *(float4*)(sp);
            float4 v1 = *(float4*)(sp + 4);
            float4 v2 = *(float4*)(sp + 8);
            float4 v3 = *(float4*)(sp + 12);
            float mx = fmaxf(fmaxf(fmaxf(v0.x, v0.y), fmaxf(v0.z, v0.w)),
                             fmaxf(fmaxf(v1.x, v1.y), fmaxf(v1.z, v1.w)));
            mx = fmaxf(mx, fmaxf(fmaxf(fmaxf(v2.x, v2.y), fmaxf(v2.z, v2.w)),
                                 fmaxf(fmaxf(v3.x, v3.y), fmaxf(v3.z, v3.w))));
            mx = fmaxf(mx, __shfl_xor_sync(0xFFFFFFFFu, mx, 1));
            mx = fmaxf(mx, __shfl_xor_sync(0xFFFFFFFFu, mx, 2));
            const float mo = mrow[row];
            const float mn = fmaxf(mo, mx);
            const float alpha = __expf(mo - mn);
            v0.x = __expf(v0.x - mn); v0.y = __expf(v0.y - mn);
            v0.z = __expf(v0.z - mn); v0.w = __expf(v0.w - mn);
            v1.x = __expf(v1.x - mn); v1.y = __expf(v1.y - mn);
            v1.z = __expf(v1.z - mn); v1.w = __expf(v1.w - mn);
            v2.x = __expf(v2.x - mn); v2.y = __expf(v2.y - mn);
            v2.z = __expf(v2.z - mn); v2.w = __expf(v2.w - mn);
            v3.x = __expf(v3.x - mn); v3.y = __expf(v3.y - mn);
            v3.z = __expf(v3.z - mn); v3.w = __expf(v3.w - mn);
            float s = (v0.x + v0.y + v0.z + v0.w) + (v1.x + v1.y + v1.z + v1.w)
                    + (v2.x + v2.y + v2.z + v2.w) + (v3.x + v3.y + v3.z + v3.w);
            v0.x = to_tf32(v0.x); v0.y = to_tf32(v0.y);
            v0.z = to_tf32(v0.z); v0.w = to_tf32(v0.w);
            v1.x = to_tf32(v1.x); v1.y = to_tf32(v1.y);
            v1.z = to_tf32(v1.z); v1.w = to_tf32(v1.w);
            v2.x = to_tf32(v2.x); v2.y = to_tf32(v2.y);
            v2.z = to_tf32(v2.z); v2.w = to_tf32(v2.w);
            v3.x = to_tf32(v3.x); v3.y = to_tf32(v3.y);
            v3.z = to_tf32(v3.z); v3.w = to_tf32(v3.w);
            *(float4*)(sp)      = v0;
            *(float4*)(sp + 4)  = v1;
            *(float4*)(sp + 8)  = v2;
            *(float4*)(sp + 12) = v3;
            s += __shfl_xor_sync(0xFFFFFFFFu, s, 1);
            s += __shfl_xor_sync(0xFFFFFFFFu, s, 2);
            if (part == 0) {
                mrow[row] = mn;
                lrow[row] = lrow[row] * alpha + s;
                arow[row] = alpha;
            }
        }
        // V(kt) [+K(kt+1)] must have landed; publish with the softmax barrier
        asm volatile("cp.async.wait_group 0;" ::: "memory");
        __syncthreads();

        // --- rescale O accumulators and P @ V ---
        {
            const float a0 = arow[wm * 16 + gid];
            const float a1 = arow[wm * 16 + gid + 8];
#pragma unroll
            for (int nt = 0; nt < 8; nt++) {
                oacc[nt][0] *= a0; oacc[nt][1] *= a0;
                oacc[nt][2] *= a1; oacc[nt][3] *= a1;
            }
#pragma unroll
            for (int ks = 0; ks < 8; ks++) {
                const int kc = ks * 8;
                const int rA = wm * 16 + gid;
                const float a0f = Ss[rA * ASSTR + kc + tig];
                const float a1f = Ss[(rA + 8) * ASSTR + kc + tig];
                const float a2f = Ss[rA * ASSTR + kc + tig + 4];
                const float a3f = Ss[(rA + 8) * ASSTR + kc + tig + 4];
#pragma unroll
                for (int nt = 0; nt < 8; nt++) {
                    const int n0 = wn * 64 + nt * 8;
                    const float b0 = Vs[(kc + tig) * AVSTR + n0 + gid];
                    const float b1 = Vs[(kc + tig + 4) * AVSTR + n0 + gid];
                    mma_tf32_16x8x8(oacc[nt][0], oacc[nt][1], oacc[nt][2], oacc[nt][3],
                                    a0f, a1f, a2f, a3f, b0, b1);
                }
            }
        }
        __syncthreads();   // protect Vs/Ss before next iteration's overwrite
    }

    // --- normalize + write out (tf32-rounded for the out-projection) ---
    {
        const int r0 = wm * 16 + gid;
        const int r1 = r0 + 8;
        const float inv0 = 1.0f / lrow[r0];
        const float inv1 = 1.0f / lrow[r1];
        const size_t ob0 = (size_t)(rowbase + q0 + r0) * HID + h * Dh;
        const size_t ob1 = (size_t)(rowbase + q0 + r1) * HID + h * Dh;
#pragma unroll
        for (int nt = 0; nt < 8; nt++) {
            const int col = wn * 64 + nt * 8 + 2 * tig;
            *(float2*)(out + ob0 + col) =
                make_float2(to_tf32(oacc[nt][0] * inv0), to_tf32(oacc[nt][1] * inv0));
            *(float2*)(out + ob1 + col) =
                make_float2(to_tf32(oacc[nt][2] * inv1), to_tf32(oacc[nt][3] * inv1));
        }
    }
}

// ---------------------------------------------------------------------------
// kernel_launch
// ---------------------------------------------------------------------------
extern "C" void kernel_launch(void* const* d_in, const int* in_sizes, int n_in,
                              void* d_out, int out_size) {
    const float* x    = (const float*)d_in[0];
    const float* cosb = (const float*)d_in[1];
    const float* sinb = (const float*)d_in[2];
    const float* kci  = (const float*)d_in[3];
    const float* vci  = (const float*)d_in[4];
    const int*   slot = (const int*)d_in[5];
    const float* Wqkv = (const float*)d_in[6];
    const float* bqkv = (const float*)d_in[7];
    const float* Wo   = (const float*)d_in[8];

    float* out = (float*)d_out;
    float* kc  = out + OUT_ELEMS;
    float* vc  = kc + CACHE_ELEMS;

    float* qkv;  cudaGetSymbolAddress((void**)&qkv,  g_qkv);
    float* attn; cudaGetSymbolAddress((void**)&attn, g_attn);
    float* xe;   cudaGetSymbolAddress((void**)&xe,   g_x);
    float* w1e;  cudaGetSymbolAddress((void**)&w1e,  g_w1);
    float* w2e;  cudaGetSymbolAddress((void**)&w2e,  g_w2);

    cudaFuncSetAttribute(attn_mma_kernel,
                         cudaFuncAttributeMaxDynamicSharedMemorySize,
                         ATT2_SMEM_FLOATS * (int)sizeof(float));
    cudaFuncSetAttribute(gemm_mma_kernel,
                         cudaFuncAttributeMaxDynamicSharedMemorySize,
                         G_SMEM_FLOATS * (int)sizeof(float));

    // 1. seed caches with the input caches
    cudaMemcpyAsync(kc, kci, CACHE_ELEMS * sizeof(float), cudaMemcpyDeviceToDevice);
    cudaMemcpyAsync(vc, vci, CACHE_ELEMS * sizeof(float), cudaMemcpyDeviceToDevice);

    // 2. tf32 pre-rounding of GEMM operands
    tf32_round_kernel<<<(Tn * HID / 4 + 255) / 256, 256>>>(x,    xe,  Tn * HID / 4);
    tf32_round_kernel<<<(NQKV * HID / 4 + 255) / 256, 256>>>(Wqkv, w1e, NQKV * HID / 4);
    tf32_round_kernel<<<(HID * HID / 4 + 255) / 256, 256>>>(Wo,   w2e, HID * HID / 4);

    // 3. QKV projection (cp.async tf32 mma GEMM)
    {
        dim3 grid(NQKV / 128, Tn / 128);
        gemm_mma_kernel<<<grid, 256, G_SMEM_FLOATS * sizeof(float)>>>(
            xe, w1e, bqkv, qkv, Tn, NQKV, HID);
    }

    // 4. RoPE in place (+tf32 rounding) + exact cache scatter
    rope_scatter_kernel<<<Tn, 256>>>(qkv, cosb, sinb, slot, kc, vc);

    // 5. causal GQA flash attention (cp.async-pipelined tensor cores)
    {
        dim3 grid(Sc / 128, Hq, Bc);
        attn_mma_kernel<<<grid, 512, ATT2_SMEM_FLOATS * sizeof(float)>>>(qkv, attn);
    }

    // 6. output projection (cp.async tf32 mma GEMM)
    {
        dim3 grid(HID / 128, Tn / 128);
        gemm_mma_kernel<<<grid, 256, G_SMEM_FLOATS * sizeof(float)>>>(
            attn, w2e, nullptr, out, Tn, HID, HID);
    }
}